// round 1
// baseline (speedup 1.0000x reference)
#include <cuda_runtime.h>
#include <math.h>

#define NN 50000
#define NE 800000
#define FIN 64
#define HD 96
#define H4 24        // HD / 4
#define NG 256

// ---------------- scratch (device globals; no runtime allocation) -----------
__device__ __align__(16) float g_xw[NN * HD];
__device__ __align__(16) float g_agg[NN * HD];
__device__ float g_dinv[NN];
__device__ float g_norm[NE];
__device__ int   g_deg[NN];
__device__ float g_gate[NN];
__device__ float g_gmax[NG];
__device__ float g_gden[NG];
__device__ __align__(16) float g_att[2][NG * FIN];
__device__ __align__(16) float g_pool[2][NG * HD];
__device__ int   g_cnt[2][NG];

// ---------------- helpers ----------------------------------------------------
__device__ __forceinline__ void red4(float* p, float4 v) {
    asm volatile("red.global.add.v4.f32 [%0], {%1,%2,%3,%4};"
                 :: "l"(p), "f"(v.x), "f"(v.y), "f"(v.z), "f"(v.w) : "memory");
}

__device__ __forceinline__ void atomicMaxFloat(float* addr, float val) {
    int* ai = (int*)addr;
    int old = *ai;
    while (true) {
        float f = __int_as_float(old);
        if (f >= val) break;
        int assumed = old;
        old = atomicCAS(ai, assumed, __float_as_int(val));
        if (old == assumed) break;
    }
}

// ---------------- init per side ----------------------------------------------
__global__ void k_init(int side) {
    int i = blockIdx.x * blockDim.x + threadIdx.x;
    if (i < NN) g_deg[i] = 0;
    if (i < NG) { g_gmax[i] = -INFINITY; g_gden[i] = 0.f; g_cnt[side][i] = 0; }
    if (i < NG * FIN) g_att[side][i] = 0.f;
    if (i < NG * HD)  g_pool[side][i] = 0.f;
}

__global__ void k_deg(const int* __restrict__ ei) {
    int e = blockIdx.x * blockDim.x + threadIdx.x;
    if (e < NE) atomicAdd(&g_deg[ei[NE + e]], 1);
}

__global__ void k_dinv() {
    int i = blockIdx.x * blockDim.x + threadIdx.x;
    if (i < NN) g_dinv[i] = rsqrtf((float)g_deg[i] + 1.0f);
}

__global__ void k_norm(const int* __restrict__ ei) {
    int e = blockIdx.x * blockDim.x + threadIdx.x;
    if (e < NE) g_norm[e] = g_dinv[ei[e]] * g_dinv[ei[NE + e]];
}

// ---------------- attention gate: gate = relu(x@gW1+gb1)@gW2 + gb2 ----------
__global__ void k_gate(const float* __restrict__ x, const int* __restrict__ batch,
                       const float* __restrict__ gW1, const float* __restrict__ gb1,
                       const float* __restrict__ gW2, const float* __restrict__ gb2) {
    int lane = threadIdx.x & 31;
    int n = blockIdx.x * (blockDim.x >> 5) + (threadIdx.x >> 5);
    if (n >= NN) return;
    float xa = x[n * FIN + lane];
    float xb = x[n * FIN + 32 + lane];
    float acc0 = gb1[lane];
    float acc1 = gb1[lane + 32];
#pragma unroll
    for (int k = 0; k < FIN; k++) {
        float xk = __shfl_sync(0xffffffffu, (k < 32) ? xa : xb, k & 31);
        acc0 += xk * gW1[k * FIN + lane];
        acc1 += xk * gW1[k * FIN + lane + 32];
    }
    float h = fmaxf(acc0, 0.f) * gW2[lane] + fmaxf(acc1, 0.f) * gW2[lane + 32];
#pragma unroll
    for (int o = 16; o > 0; o >>= 1) h += __shfl_down_sync(0xffffffffu, h, o);
    if (lane == 0) {
        float gate = h + gb2[0];
        g_gate[n] = gate;
        atomicMaxFloat(&g_gmax[batch[n]], gate);
    }
}

__global__ void k_expsum(const int* __restrict__ batch) {
    int n = blockIdx.x * blockDim.x + threadIdx.x;
    if (n < NN) {
        int b = batch[n];
        float e = expf(g_gate[n] - g_gmax[b]);
        g_gate[n] = e;
        atomicAdd(&g_gden[b], e);
    }
}

__global__ void k_attpool(const float* __restrict__ x, const int* __restrict__ batch, int side) {
    int idx = blockIdx.x * blockDim.x + threadIdx.x;     // NN * 16 chunks
    if (idx >= NN * (FIN / 4)) return;
    int n = idx >> 4, j = idx & 15;
    int b = batch[n];
    float alpha = g_gate[n] / g_gden[b];
    float4 v = ((const float4*)x)[n * (FIN / 4) + j];
    v.x *= alpha; v.y *= alpha; v.z *= alpha; v.w *= alpha;
    red4(&g_att[side][b * FIN + j * 4], v);
}

// ---------------- tiled SIMT GEMM: out[N,96] = (reluIn? relu(X):X)[N,K] @ W[K,96]
// Block tile: 24 rows x 96 cols; blockDim (24,6); thread = 4 rows x 4 cols.
#define GROWS 24
__global__ void k_gemm(const float* __restrict__ Xext, int useAgg,
                       const float* __restrict__ W, int K, int reluIn) {
    const float* X = useAgg ? g_agg : Xext;
    __shared__ __align__(16) float Ws[HD * HD];          // K*96 used
    __shared__ float Xs[GROWS * (HD + 1)];               // stride K+1 at runtime
    const int tid = threadIdx.y * 24 + threadIdx.x;
    const int nth = 24 * 6;
    const int KS = K + 1;

    for (int i = tid; i < K * HD; i += nth) Ws[i] = W[i];

    for (int t0 = blockIdx.x * GROWS; t0 < NN; t0 += gridDim.x * GROWS) {
        __syncthreads();
        for (int i = tid; i < GROWS * K; i += nth) {
            int r = i / K, k = i - r * K;
            int row = t0 + r;
            float v = (row < NN) ? X[row * K + k] : 0.f;
            if (reluIn) v = fmaxf(v, 0.f);
            Xs[r * KS + k] = v;
        }
        __syncthreads();
        int rb = threadIdx.y * 4;
        int c4 = threadIdx.x;
        float4 a0 = {0,0,0,0}, a1 = {0,0,0,0}, a2 = {0,0,0,0}, a3 = {0,0,0,0};
        const float4* Ws4 = (const float4*)Ws;
        for (int k = 0; k < K; k++) {
            float4 w = Ws4[k * H4 + c4];
            float x0 = Xs[(rb + 0) * KS + k];
            float x1 = Xs[(rb + 1) * KS + k];
            float x2 = Xs[(rb + 2) * KS + k];
            float x3 = Xs[(rb + 3) * KS + k];
            a0.x += x0 * w.x; a0.y += x0 * w.y; a0.z += x0 * w.z; a0.w += x0 * w.w;
            a1.x += x1 * w.x; a1.y += x1 * w.y; a1.z += x1 * w.z; a1.w += x1 * w.w;
            a2.x += x2 * w.x; a2.y += x2 * w.y; a2.z += x2 * w.z; a2.w += x2 * w.w;
            a3.x += x3 * w.x; a3.y += x3 * w.y; a3.z += x3 * w.z; a3.w += x3 * w.w;
        }
        float4* out4 = (float4*)g_xw;
        int r0 = t0 + rb;
        if (r0 + 0 < NN) out4[(r0 + 0) * H4 + c4] = a0;
        if (r0 + 1 < NN) out4[(r0 + 1) * H4 + c4] = a1;
        if (r0 + 2 < NN) out4[(r0 + 2) * H4 + c4] = a2;
        if (r0 + 3 < NN) out4[(r0 + 3) * H4 + c4] = a3;
    }
}

// ---------------- agg init: agg = dinv^2 * xw + bias --------------------------
__global__ void k_initagg(const float* __restrict__ bias) {
    int idx = blockIdx.x * blockDim.x + threadIdx.x;     // NN * 24
    if (idx >= NN * H4) return;
    int n = idx / H4, j = idx - n * H4;
    float d = g_dinv[n];
    float s = d * d;
    float4 v = ((const float4*)g_xw)[idx];
    float4 b = ((const float4*)bias)[j];
    v.x = fmaf(s, v.x, b.x); v.y = fmaf(s, v.y, b.y);
    v.z = fmaf(s, v.z, b.z); v.w = fmaf(s, v.w, b.w);
    ((float4*)g_agg)[idx] = v;
}

// ---------------- edge scatter: agg[dst] += norm * xw[src] -------------------
__global__ void k_scatter(const int* __restrict__ ei) {
    int idx = blockIdx.x * blockDim.x + threadIdx.x;     // NE * 24
    if (idx >= NE * H4) return;
    int e = idx / H4, j = idx - e * H4;
    int s = __ldg(&ei[e]);
    int d = __ldg(&ei[NE + e]);
    float nv = __ldg(&g_norm[e]);
    float4 v = __ldg(&((const float4*)g_xw)[s * H4 + j]);
    v.x *= nv; v.y *= nv; v.z *= nv; v.w *= nv;
    red4(&g_agg[d * HD + j * 4], v);
}

// ---------------- mean pool accumulation -------------------------------------
__global__ void k_meanpool(const int* __restrict__ batch, int side) {
    int idx = blockIdx.x * blockDim.x + threadIdx.x;     // NN * 24
    if (idx >= NN * H4) return;
    int n = idx / H4, j = idx - n * H4;
    int b = batch[n];
    float4 v = ((const float4*)g_agg)[idx];
    red4(&g_pool[side][b * HD + j * 4], v);
    if (j == 0) atomicAdd(&g_cnt[side][b], 1);
}

// ---------------- final MLP ---------------------------------------------------
__global__ void k_final(const float* __restrict__ lW0, const float* __restrict__ lb0,
                        const float* __restrict__ lW1, const float* __restrict__ lb1,
                        float* __restrict__ out) {
    int g = blockIdx.x;
    int j = threadIdx.x;                                 // 96 threads
    __shared__ float cat[2 * HD + 2 * FIN];              // 320
    __shared__ float red[HD];
    for (int i = j; i < 2 * HD + 2 * FIN; i += HD) {
        float v;
        if (i < HD)            v = g_pool[0][g * HD + i] / fmaxf((float)g_cnt[0][g], 1.f);
        else if (i < 2 * HD)   v = g_pool[1][g * HD + (i - HD)] / fmaxf((float)g_cnt[1][g], 1.f);
        else if (i < 2 * HD + FIN) v = g_att[0][g * FIN + (i - 2 * HD)];
        else                   v = g_att[1][g * FIN + (i - 2 * HD - FIN)];
        cat[i] = v;
    }
    __syncthreads();
    float acc = lb0[j];
#pragma unroll 8
    for (int i = 0; i < 2 * HD + 2 * FIN; i++)
        acc += cat[i] * lW0[i * HD + j];
    red[j] = fmaxf(acc, 0.f) * lW1[j];
    __syncthreads();
    if (j == 0) {
        float s = lb1[0];
        for (int t = 0; t < HD; t++) s += red[t];
        out[g] = s;
    }
}

// ---------------- host launcher ----------------------------------------------
extern "C" void kernel_launch(void* const* d_in, const int* in_sizes, int n_in,
                              void* d_out, int out_size) {
    const float* gW1 = (const float*)d_in[20];
    const float* gb1 = (const float*)d_in[21];
    const float* gW2 = (const float*)d_in[22];
    const float* gb2 = (const float*)d_in[23];
    const float* lW0 = (const float*)d_in[24];
    const float* lb0 = (const float*)d_in[25];
    const float* lW1 = (const float*)d_in[26];
    const float* lb1 = (const float*)d_in[27];

    const int TB = 256;
    const int GB_N  = (NN + TB - 1) / TB;
    const int GB_E  = (NE + TB - 1) / TB;
    const int GB_NH = (NN * H4 + TB - 1) / TB;
    const int GB_EH = (NE * H4 + TB - 1) / TB;
    const int GB_AT = (NN * (FIN / 4) + TB - 1) / TB;
    const int GEMM_GRID = 592;
    dim3 gemmBlk(24, 6);

    for (int side = 0; side < 2; side++) {
        const float* x     = (const float*)d_in[side];        // x_p / x_d
        const int*   ei    = (const int*)d_in[4 + side];      // edge_index
        const int*   batch = (const int*)d_in[6 + side];      // batch
        const float* W0 = (const float*)d_in[8 + 6 * side];
        const float* b0 = (const float*)d_in[9 + 6 * side];
        const float* W1 = (const float*)d_in[10 + 6 * side];
        const float* b1 = (const float*)d_in[11 + 6 * side];
        const float* W2 = (const float*)d_in[12 + 6 * side];
        const float* b2 = (const float*)d_in[13 + 6 * side];

        k_init<<<GB_N, TB>>>(side);
        k_deg<<<GB_E, TB>>>(ei);
        k_dinv<<<GB_N, TB>>>();
        k_norm<<<GB_E, TB>>>(ei);

        // attention pooling on raw features
        k_gate<<<(NN + 7) / 8, 256>>>(x, batch, gW1, gb1, gW2, gb2);
        k_expsum<<<GB_N, TB>>>(batch);
        k_attpool<<<GB_AT, TB>>>(x, batch, side);

        // layer 0 (K = 64, no input relu)
        k_gemm<<<GEMM_GRID, gemmBlk>>>(x, 0, W0, FIN, 0);
        k_initagg<<<GB_NH, TB>>>(b0);
        k_scatter<<<GB_EH, TB>>>(ei);
        // layer 1 (K = 96, relu on input)
        k_gemm<<<GEMM_GRID, gemmBlk>>>(nullptr, 1, W1, HD, 1);
        k_initagg<<<GB_NH, TB>>>(b1);
        k_scatter<<<GB_EH, TB>>>(ei);
        // layer 2 (K = 96, relu on input, no relu on output)
        k_gemm<<<GEMM_GRID, gemmBlk>>>(nullptr, 1, W2, HD, 1);
        k_initagg<<<GB_NH, TB>>>(b2);
        k_scatter<<<GB_EH, TB>>>(ei);

        k_meanpool<<<GB_NH, TB>>>(batch, side);
    }

    k_final<<<NG, HD>>>(lW0, lb0, lW1, lb1, (float*)d_out);
}

// round 3
// speedup vs baseline: 1.3593x; 1.3593x over previous
#include <cuda_runtime.h>
#include <math.h>

#define NN 50000
#define NE 800000
#define FIN 64
#define HD 96
#define H4 24        // HD / 4
#define NG 256
#define SCB 512
#define NSCB ((NN + SCB - 1) / SCB)   // 98

// ---------------- scratch (device globals; no runtime allocation) -----------
__device__ __align__(16) float g_xw[NN * HD];     // GEMM output
__device__ __align__(16) float g_agg[NN * HD];    // gather output (K<=96)
__device__ float g_dinv[NN];
__device__ int   g_deg[NN];
__device__ int   g_coff[NN + 1];                  // CSR offsets (by dst)
__device__ int   g_cur[NN];                       // fill cursors
__device__ int   g_csrc[NE];                      // CSR: src node
__device__ float g_cdv[NE];                       // CSR: dinv[src]
__device__ int   g_bsum[NSCB];
__device__ float g_gate[NN];
__device__ float g_gmax[NG];
__device__ float g_gden[NG];
__device__ __align__(16) float g_att[2][NG * FIN];
__device__ __align__(16) float g_pool[2][NG * HD];
__device__ int   g_cnt[2][NG];

// ---------------- helpers ----------------------------------------------------
__device__ __forceinline__ void red4(float* p, float4 v) {
    asm volatile("red.global.add.v4.f32 [%0], {%1,%2,%3,%4};"
                 :: "l"(p), "f"(v.x), "f"(v.y), "f"(v.z), "f"(v.w) : "memory");
}

__device__ __forceinline__ void atomicMaxFloat(float* addr, float val) {
    int* ai = (int*)addr;
    int old = *ai;
    while (true) {
        float f = __int_as_float(old);
        if (f >= val) break;
        int assumed = old;
        old = atomicCAS(ai, assumed, __float_as_int(val));
        if (old == assumed) break;
    }
}

// ---------------- init per side ----------------------------------------------
__global__ void k_init(int side) {
    int i = blockIdx.x * blockDim.x + threadIdx.x;
    if (i < NN) g_deg[i] = 0;
    if (i < NG) { g_gmax[i] = -INFINITY; g_gden[i] = 0.f; g_cnt[side][i] = 0; }
    if (i < NG * FIN) g_att[side][i] = 0.f;
    if (i < NG * HD)  g_pool[side][i] = 0.f;
}

__global__ void k_deg(const int* __restrict__ ei) {
    int e = blockIdx.x * blockDim.x + threadIdx.x;
    if (e < NE) atomicAdd(&g_deg[ei[NE + e]], 1);
}

__global__ void k_dinv() {
    int i = blockIdx.x * blockDim.x + threadIdx.x;
    if (i < NN) g_dinv[i] = rsqrtf((float)g_deg[i] + 1.0f);
}

// ---------------- CSR build: scan of degrees, then fill ----------------------
__global__ void k_scan1() {
    __shared__ int s[SCB];
    int i = blockIdx.x * SCB + threadIdx.x;
    s[threadIdx.x] = (i < NN) ? g_deg[i] : 0;
    __syncthreads();
    for (int o = SCB / 2; o > 0; o >>= 1) {
        if (threadIdx.x < o) s[threadIdx.x] += s[threadIdx.x + o];
        __syncthreads();
    }
    if (threadIdx.x == 0) g_bsum[blockIdx.x] = s[0];
}

__global__ void k_scan2() {
    if (threadIdx.x == 0) {
        int acc = 0;
        for (int b = 0; b < NSCB; b++) { int t = g_bsum[b]; g_bsum[b] = acc; acc += t; }
        g_coff[NN] = acc;
    }
}

__global__ void k_scan3() {
    __shared__ int s[SCB];
    int i = blockIdx.x * SCB + threadIdx.x;
    int t = threadIdx.x;
    int v = (i < NN) ? g_deg[i] : 0;
    s[t] = v;
    __syncthreads();
    for (int o = 1; o < SCB; o <<= 1) {
        int a = (t >= o) ? s[t - o] : 0;
        __syncthreads();
        s[t] += a;
        __syncthreads();
    }
    if (i < NN) {
        int off = g_bsum[blockIdx.x] + s[t] - v;   // exclusive
        g_coff[i] = off;
        g_cur[i] = off;
    }
}

__global__ void k_csrfill(const int* __restrict__ ei) {
    int e = blockIdx.x * blockDim.x + threadIdx.x;
    if (e < NE) {
        int s = ei[e], d = ei[NE + e];
        int slot = atomicAdd(&g_cur[d], 1);
        g_csrc[slot] = s;
        g_cdv[slot] = g_dinv[s];
    }
}

// ---------------- attention gate ----------------------------------------------
__global__ void k_gate(const float* __restrict__ x, const int* __restrict__ batch,
                       const float* __restrict__ gW1, const float* __restrict__ gb1,
                       const float* __restrict__ gW2, const float* __restrict__ gb2) {
    int lane = threadIdx.x & 31;
    int n = blockIdx.x * (blockDim.x >> 5) + (threadIdx.x >> 5);
    if (n >= NN) return;
    float xa = x[n * FIN + lane];
    float xb = x[n * FIN + 32 + lane];
    float acc0 = gb1[lane];
    float acc1 = gb1[lane + 32];
#pragma unroll
    for (int k = 0; k < FIN; k++) {
        float xk = __shfl_sync(0xffffffffu, (k < 32) ? xa : xb, k & 31);
        acc0 += xk * gW1[k * FIN + lane];
        acc1 += xk * gW1[k * FIN + lane + 32];
    }
    float h = fmaxf(acc0, 0.f) * gW2[lane] + fmaxf(acc1, 0.f) * gW2[lane + 32];
#pragma unroll
    for (int o = 16; o > 0; o >>= 1) h += __shfl_down_sync(0xffffffffu, h, o);
    if (lane == 0) {
        float gate = h + gb2[0];
        g_gate[n] = gate;
        atomicMaxFloat(&g_gmax[batch[n]], gate);
    }
}

__global__ void k_expsum(const int* __restrict__ batch, int side) {
    int n = blockIdx.x * blockDim.x + threadIdx.x;
    if (n < NN) {
        int b = batch[n];
        float e = expf(g_gate[n] - g_gmax[b]);
        g_gate[n] = e;
        atomicAdd(&g_gden[b], e);
        atomicAdd(&g_cnt[side][b], 1);
    }
}

__global__ void k_attpool(const float* __restrict__ x, const int* __restrict__ batch, int side) {
    int idx = blockIdx.x * blockDim.x + threadIdx.x;     // NN * 16 chunks
    if (idx >= NN * (FIN / 4)) return;
    int n = idx >> 4, j = idx & 15;
    int b = batch[n];
    float alpha = g_gate[n] / g_gden[b];
    float4 v = ((const float4*)x)[n * (FIN / 4) + j];
    v.x *= alpha; v.y *= alpha; v.z *= alpha; v.w *= alpha;
    red4(&g_att[side][b * FIN + j * 4], v);
}

// ---------------- CSR gather: agg[n] = dinv[n]^2*feat[n] + sum dinv[n]*dv[e]*feat[src]
// useXw selects g_xw (device-side!) vs external feat. reluIn relus feat on read.
__global__ void k_gather(const float* __restrict__ featExt, int useXw, int K4, int reluIn) {
    int idx = blockIdx.x * blockDim.x + threadIdx.x;
    if (idx >= NN * K4) return;
    const float4* f4 = useXw ? (const float4*)g_xw : (const float4*)featExt;
    int n = idx / K4, j = idx - n * K4;
    int p = __ldg(&g_coff[n]);
    int end = __ldg(&g_coff[n + 1]);
    float dv = g_dinv[n];

    float4 v = __ldg(&f4[n * K4 + j]);
    if (reluIn) { v.x = fmaxf(v.x, 0.f); v.y = fmaxf(v.y, 0.f); v.z = fmaxf(v.z, 0.f); v.w = fmaxf(v.w, 0.f); }
    float s = dv * dv;
    float4 acc = { s * v.x, s * v.y, s * v.z, s * v.w };

    for (; p + 1 < end; p += 2) {
        int s0 = __ldg(&g_csrc[p]);
        int s1 = __ldg(&g_csrc[p + 1]);
        float w0 = dv * __ldg(&g_cdv[p]);
        float w1 = dv * __ldg(&g_cdv[p + 1]);
        float4 a = __ldg(&f4[s0 * K4 + j]);
        float4 b = __ldg(&f4[s1 * K4 + j]);
        if (reluIn) {
            a.x = fmaxf(a.x, 0.f); a.y = fmaxf(a.y, 0.f); a.z = fmaxf(a.z, 0.f); a.w = fmaxf(a.w, 0.f);
            b.x = fmaxf(b.x, 0.f); b.y = fmaxf(b.y, 0.f); b.z = fmaxf(b.z, 0.f); b.w = fmaxf(b.w, 0.f);
        }
        acc.x += w0 * a.x + w1 * b.x;
        acc.y += w0 * a.y + w1 * b.y;
        acc.z += w0 * a.z + w1 * b.z;
        acc.w += w0 * a.w + w1 * b.w;
    }
    if (p < end) {
        int s0 = __ldg(&g_csrc[p]);
        float w0 = dv * __ldg(&g_cdv[p]);
        float4 a = __ldg(&f4[s0 * K4 + j]);
        if (reluIn) { a.x = fmaxf(a.x, 0.f); a.y = fmaxf(a.y, 0.f); a.z = fmaxf(a.z, 0.f); a.w = fmaxf(a.w, 0.f); }
        acc.x += w0 * a.x; acc.y += w0 * a.y; acc.z += w0 * a.z; acc.w += w0 * a.w;
    }
    ((float4*)g_agg)[idx] = acc;
}

// ---------------- tiled SIMT GEMM: g_xw[N,96] = g_agg[N,K] @ W[K,96] + bias
// fusePool: skip store, reduce rows into g_pool[side] by batch instead.
#define GROWS 24
__global__ void k_gemm(const float* __restrict__ W, const float* __restrict__ bias,
                       int K, int fusePool, const int* __restrict__ batch, int side) {
    const float* X = g_agg;
    __shared__ __align__(16) float Ws[HD * HD];
    __shared__ float Xs[GROWS * (HD + 1)];
    const int tid = threadIdx.y * 24 + threadIdx.x;
    const int nth = 24 * 6;
    const int KS = K + 1;

    for (int i = tid; i < K * HD; i += nth) Ws[i] = W[i];

    int rb = threadIdx.y * 4;
    int c4 = threadIdx.x;
    float4 bb = __ldg(&((const float4*)bias)[c4]);

    for (int t0 = blockIdx.x * GROWS; t0 < NN; t0 += gridDim.x * GROWS) {
        __syncthreads();
        for (int i = tid; i < GROWS * K; i += nth) {
            int r = i / K, k = i - r * K;
            int row = t0 + r;
            Xs[r * KS + k] = (row < NN) ? X[row * K + k] : 0.f;
        }
        __syncthreads();
        float4 a0 = bb, a1 = bb, a2 = bb, a3 = bb;
        const float4* Ws4 = (const float4*)Ws;
        for (int k = 0; k < K; k++) {
            float4 w = Ws4[k * H4 + c4];
            float x0 = Xs[(rb + 0) * KS + k];
            float x1 = Xs[(rb + 1) * KS + k];
            float x2 = Xs[(rb + 2) * KS + k];
            float x3 = Xs[(rb + 3) * KS + k];
            a0.x += x0 * w.x; a0.y += x0 * w.y; a0.z += x0 * w.z; a0.w += x0 * w.w;
            a1.x += x1 * w.x; a1.y += x1 * w.y; a1.z += x1 * w.z; a1.w += x1 * w.w;
            a2.x += x2 * w.x; a2.y += x2 * w.y; a2.z += x2 * w.z; a2.w += x2 * w.w;
            a3.x += x3 * w.x; a3.y += x3 * w.y; a3.z += x3 * w.z; a3.w += x3 * w.w;
        }
        int r0 = t0 + rb;
        if (!fusePool) {
            float4* out4 = (float4*)g_xw;
            if (r0 + 0 < NN) out4[(r0 + 0) * H4 + c4] = a0;
            if (r0 + 1 < NN) out4[(r0 + 1) * H4 + c4] = a1;
            if (r0 + 2 < NN) out4[(r0 + 2) * H4 + c4] = a2;
            if (r0 + 3 < NN) out4[(r0 + 3) * H4 + c4] = a3;
        } else {
            if (r0 + 0 < NN) red4(&g_pool[side][batch[r0 + 0] * HD + c4 * 4], a0);
            if (r0 + 1 < NN) red4(&g_pool[side][batch[r0 + 1] * HD + c4 * 4], a1);
            if (r0 + 2 < NN) red4(&g_pool[side][batch[r0 + 2] * HD + c4 * 4], a2);
            if (r0 + 3 < NN) red4(&g_pool[side][batch[r0 + 3] * HD + c4 * 4], a3);
        }
    }
}

// ---------------- final MLP ---------------------------------------------------
__global__ void k_final(const float* __restrict__ lW0, const float* __restrict__ lb0,
                        const float* __restrict__ lW1, const float* __restrict__ lb1,
                        float* __restrict__ out) {
    int g = blockIdx.x;
    int j = threadIdx.x;                                 // 96 threads
    __shared__ float cat[2 * HD + 2 * FIN];              // 320
    __shared__ float red[HD];
    for (int i = j; i < 2 * HD + 2 * FIN; i += HD) {
        float v;
        if (i < HD)            v = g_pool[0][g * HD + i] / fmaxf((float)g_cnt[0][g], 1.f);
        else if (i < 2 * HD)   v = g_pool[1][g * HD + (i - HD)] / fmaxf((float)g_cnt[1][g], 1.f);
        else if (i < 2 * HD + FIN) v = g_att[0][g * FIN + (i - 2 * HD)];
        else                   v = g_att[1][g * FIN + (i - 2 * HD - FIN)];
        cat[i] = v;
    }
    __syncthreads();
    float acc = lb0[j];
#pragma unroll 8
    for (int i = 0; i < 2 * HD + 2 * FIN; i++)
        acc += cat[i] * lW0[i * HD + j];
    red[j] = fmaxf(acc, 0.f) * lW1[j];
    __syncthreads();
    if (j == 0) {
        float s = lb1[0];
        for (int t = 0; t < HD; t++) s += red[t];
        out[g] = s;
    }
}

// ---------------- host launcher ----------------------------------------------
extern "C" void kernel_launch(void* const* d_in, const int* in_sizes, int n_in,
                              void* d_out, int out_size) {
    const float* gW1 = (const float*)d_in[20];
    const float* gb1 = (const float*)d_in[21];
    const float* gW2 = (const float*)d_in[22];
    const float* gb2 = (const float*)d_in[23];
    const float* lW0 = (const float*)d_in[24];
    const float* lb0 = (const float*)d_in[25];
    const float* lW1 = (const float*)d_in[26];
    const float* lb1 = (const float*)d_in[27];

    const int TB = 256;
    const int GB_N  = (NN + TB - 1) / TB;
    const int GB_E  = (NE + TB - 1) / TB;
    const int GB_G16 = (NN * 16 + TB - 1) / TB;
    const int GB_G24 = (NN * 24 + TB - 1) / TB;
    const int GEMM_GRID = 592;
    dim3 gemmBlk(24, 6);

    for (int side = 0; side < 2; side++) {
        const float* x     = (const float*)d_in[side];        // x_p / x_d
        const int*   ei    = (const int*)d_in[4 + side];      // edge_index
        const int*   batch = (const int*)d_in[6 + side];      // batch
        const float* W0 = (const float*)d_in[8 + 6 * side];
        const float* b0 = (const float*)d_in[9 + 6 * side];
        const float* W1 = (const float*)d_in[10 + 6 * side];
        const float* b1 = (const float*)d_in[11 + 6 * side];
        const float* W2 = (const float*)d_in[12 + 6 * side];
        const float* b2 = (const float*)d_in[13 + 6 * side];

        k_init<<<GB_N, TB>>>(side);
        k_deg<<<GB_E, TB>>>(ei);
        k_dinv<<<GB_N, TB>>>();

        // CSR build (by dst)
        k_scan1<<<NSCB, SCB>>>();
        k_scan2<<<1, 32>>>();
        k_scan3<<<NSCB, SCB>>>();
        k_csrfill<<<GB_E, TB>>>(ei);

        // attention pooling on raw features
        k_gate<<<(NN + 7) / 8, 256>>>(x, batch, gW1, gb1, gW2, gb2);
        k_expsum<<<GB_N, TB>>>(batch, side);
        k_attpool<<<GB_G16, TB>>>(x, batch, side);

        // layer 0: aggregate x (K=64), then GEMM 64->96
        k_gather<<<GB_G16, TB>>>(x, 0, 16, 0);
        k_gemm<<<GEMM_GRID, gemmBlk>>>(W0, b0, FIN, 0, batch, side);
        // layer 1: aggregate relu(h0) (K=96), GEMM 96->96
        k_gather<<<GB_G24, TB>>>(nullptr, 1, 24, 1);
        k_gemm<<<GEMM_GRID, gemmBlk>>>(W1, b1, HD, 0, batch, side);
        // layer 2: aggregate relu(h1), GEMM 96->96 fused with mean-pool sum
        k_gather<<<GB_G24, TB>>>(nullptr, 1, 24, 1);
        k_gemm<<<GEMM_GRID, gemmBlk>>>(W2, b2, HD, 1, batch, side);
    }

    k_final<<<NG, HD>>>(lW0, lb0, lW1, lb1, (float*)d_out);
}